// round 14
// baseline (speedup 1.0000x reference)
#include <cuda_runtime.h>
#include <cuda_bf16.h>
#include <cstdint>

typedef unsigned long long ull;

#define NEGV (-1e12f)
constexpr int Bc = 16, Tc = 100, Sc = 400, Vc = 50000, Ec = 128, Hc = 256;
constexpr int EXTV = Vc + 1000;
constexpr int MALL = Bc * Tc;   // 1600
constexpr int MPAD = 1664;      // 13 * 128
constexpr int NPAD = 50176;     // 392 * 128
constexpr int KBF  = 768;       // 3 * 256 (bf16 hi/lo split)
constexpr int BKC  = 32;        // K per chunk in mma kernel
constexpr int NCH  = KBF / BKC; // 24
constexpr int ROWH = 40;        // smem halves per row (80B, conflict-free ldmatrix)
constexpr int KSM  = 384;       // W2p rows resident in smem per CTA
constexpr int SMW_BYTES = KSM * 128 * 4;   // 192 KB

// ---------------- scratch (static device globals; no allocations) ----------
__device__ __align__(16) float g_mem[Bc * Sc * Hc];
__device__ __align__(16) float g_A1[Ec * 4 * Hc];
__device__ __align__(16) float g_A2[Hc * 4 * Hc];
__device__ __align__(16) float g_W2p[8 * 512 * 128];
__device__ __align__(16) float g_bz[4 * Hc];
__device__ __align__(16) float g_ze[MALL * 4 * Hc];
__device__ __align__(16) float g_energy[Tc * Bc * Sc];
__device__ __align__(16) float g_cat[MALL * 2 * Hc];
__device__ __align__(16) float g_feat[MALL * Hc];
__device__ int g_skey[Bc * 512];
__device__ __align__(16) unsigned short g_Abf[MPAD * KBF];         // A' bf16
__device__ __align__(16) unsigned short g_Bbf[(size_t)NPAD * KBF]; // B' bf16 (77MB)

// ---------------- f32x2 helpers --------------------------------------------
__device__ __forceinline__ ull dup2(float a) {
    ull r; asm("mov.b64 %0, {%1,%1};" : "=l"(r) : "f"(a)); return r;
}
__device__ __forceinline__ void fma2(ull& d, ull a, ull b) {
    asm("fma.rn.f32x2 %0, %1, %2, %0;" : "+l"(d) : "l"(a), "l"(b));
}
__device__ __forceinline__ ull add2(ull a, ull b) {
    ull r; asm("add.rn.f32x2 %0, %1, %2;" : "=l"(r) : "l"(a), "l"(b)); return r;
}
__device__ __forceinline__ float2 up2(ull v) {
    float2 r; asm("mov.b64 {%0,%1}, %2;" : "=f"(r.x), "=f"(r.y) : "l"(v)); return r;
}
__device__ __forceinline__ float sigm(float x) { return 1.f / (1.f + expf(-x)); }

// ---------------- DSMEM / cluster helpers ----------------------------------
__device__ __forceinline__ unsigned s2u(const void* p) {
    return (unsigned)__cvta_generic_to_shared(p);
}
__device__ __forceinline__ void stc_f(unsigned laddr, unsigned rank, float v) {
    unsigned ra;
    asm volatile("mapa.shared::cluster.u32 %0, %1, %2;" : "=r"(ra) : "r"(laddr), "r"(rank));
    asm volatile("st.shared::cluster.f32 [%0], %1;" :: "r"(ra), "f"(v));
}
__device__ __forceinline__ void stc_f2(unsigned laddr, unsigned rank, float2 v) {
    unsigned ra;
    asm volatile("mapa.shared::cluster.u32 %0, %1, %2;" : "=r"(ra) : "r"(laddr), "r"(rank));
    asm volatile("st.shared::cluster.v2.f32 [%0], {%1,%2};" :: "r"(ra), "f"(v.x), "f"(v.y));
}
#define CLUSTER_SYNC() do { \
    asm volatile("barrier.cluster.arrive.aligned;" ::: "memory"); \
    asm volatile("barrier.cluster.wait.aligned;"   ::: "memory"); } while (0)

// ---------------- cp.async helpers -----------------------------------------
__device__ __forceinline__ void cp16(unsigned d, const void* s) {
    asm volatile("cp.async.cg.shared.global [%0], [%1], 16;" :: "r"(d), "l"(s));
}
#define CP_COMMIT() asm volatile("cp.async.commit_group;" ::: "memory")
#define CP_WAIT0()  asm volatile("cp.async.wait_group 0;" ::: "memory")

// ---------------- generic GEMM (A1/A2/ze) ----------------------------------
template <int ACT, int MODE, bool GATHER>
__global__ void __launch_bounds__(256) gemm_k(
    const float* __restrict__ A, const float* __restrict__ W,
    const float* __restrict__ bias, float* __restrict__ C,
    int M, int N, int K, int lda, int ldc, const int* __restrict__ gidx)
{
    __shared__ __align__(16) float As[32][68];
    __shared__ __align__(16) float Bs[32][128];
    int tid = threadIdx.x;
    int n0 = blockIdx.x * 128;
    int m0 = blockIdx.y * 64;
    int tx = tid & 15, ty = tid >> 4;

    int arw = tid >> 2;
    int amr = m0 + arw;
    const float* Arow;
    if (GATHER) {
        int g = gidx[(amr & 15) * Tc + (amr >> 4)];
        Arow = A + (size_t)g * lda;
    } else {
        Arow = A + (size_t)amr * lda;
    }
    int akk = (tid & 3) * 8;
    int bk = tid >> 3;
    int bn = (tid & 7) * 16;

    ull acc[4][4];
#pragma unroll
    for (int i = 0; i < 4; i++)
#pragma unroll
        for (int p = 0; p < 4; p++) acc[i][p] = 0ull;

    int nch = K >> 5;
    for (int kc = 0; kc < nch; kc++) {
        float4 a0 = *reinterpret_cast<const float4*>(Arow + kc * 32 + akk);
        float4 a1 = *reinterpret_cast<const float4*>(Arow + kc * 32 + akk + 4);
        As[akk + 0][arw] = a0.x; As[akk + 1][arw] = a0.y;
        As[akk + 2][arw] = a0.z; As[akk + 3][arw] = a0.w;
        As[akk + 4][arw] = a1.x; As[akk + 5][arw] = a1.y;
        As[akk + 6][arw] = a1.z; As[akk + 7][arw] = a1.w;

        const float* Wrow = W + (size_t)(kc * 32 + bk) * N + n0 + bn;
#pragma unroll
        for (int i = 0; i < 4; i++) {
            int n = n0 + bn + 4 * i;
            float4 v = (n < N) ? *reinterpret_cast<const float4*>(Wrow + 4 * i)
                               : make_float4(0.f, 0.f, 0.f, 0.f);
            *reinterpret_cast<float4*>(&Bs[bk][bn + 4 * i]) = v;
        }
        __syncthreads();

#pragma unroll
        for (int k = 0; k < 32; k++) {
            const ull* brow = reinterpret_cast<const ull*>(&Bs[k][0]);
            ull b0 = brow[tx * 4 + 0], b1 = brow[tx * 4 + 1];
            ull b2 = brow[tx * 4 + 2], b3 = brow[tx * 4 + 3];
#pragma unroll
            for (int i = 0; i < 4; i++) {
                ull a2 = dup2(As[k][ty * 4 + i]);
                fma2(acc[i][0], a2, b0);
                fma2(acc[i][1], a2, b1);
                fma2(acc[i][2], a2, b2);
                fma2(acc[i][3], a2, b3);
            }
        }
        __syncthreads();
    }

#pragma unroll
    for (int i = 0; i < 4; i++) {
        int m = m0 + ty * 4 + i;
        int crow = (MODE == 1) ? ((m & 15) * Tc + (m >> 4)) : m;
        float* Crow = C + (size_t)crow * ldc;
#pragma unroll
        for (int p = 0; p < 4; p++) {
            int n = n0 + tx * 8 + 2 * p;
            if (n < N) {
                float2 v = up2(acc[i][p]);
                float r0 = v.x, r1 = v.y;
                if (bias) { r0 += bias[n]; r1 += bias[n + 1]; }
                if (ACT) { r0 = tanhf(r0); r1 = tanhf(r1); }
                Crow[n] = r0;
                Crow[n + 1] = r1;
            }
        }
    }
}

// ---------------- fast fp32 GEMM (memories / feat) -------------------------
template <int ACT, int MODE>
__global__ void __launch_bounds__(256, 2) gemm2_k(
    const float* __restrict__ A, const float* __restrict__ W,
    const float* __restrict__ bias, float* __restrict__ C,
    int M, int N, int K, int lda, int ldc)
{
    __shared__ __align__(16) ull   Asd[16][64];
    __shared__ __align__(16) float Bs[16][256];
    int tid = threadIdx.x;
    int n0 = blockIdx.x * 256, m0 = blockIdx.y * 64;
    int tx = tid & 15, ty = tid >> 4;

    int arow = tid >> 2;
    int akq = (tid & 3) * 4;
    const float* Ap = A + (size_t)(m0 + arow) * lda + akq;

    ull acc[4][8];
#pragma unroll
    for (int i = 0; i < 4; i++)
#pragma unroll
        for (int p = 0; p < 8; p++) acc[i][p] = 0ull;

    for (int kc = 0; kc < K; kc += 16) {
        float4 av = *reinterpret_cast<const float4*>(Ap);
        Ap += 16;
        Asd[akq + 0][arow] = dup2(av.x);
        Asd[akq + 1][arow] = dup2(av.y);
        Asd[akq + 2][arow] = dup2(av.z);
        Asd[akq + 3][arow] = dup2(av.w);
#pragma unroll
        for (int i = 0; i < 4; i++) {
            int e = i * 256 + tid;
            int rk = e >> 6, cc = (e & 63) * 4;
            int n = n0 + cc;
            float4 v = (n < N) ? *reinterpret_cast<const float4*>(W + (size_t)(kc + rk) * N + n)
                               : make_float4(0.f, 0.f, 0.f, 0.f);
            *reinterpret_cast<float4*>(&Bs[rk][cc]) = v;
        }
        __syncthreads();

#pragma unroll
        for (int k = 0; k < 16; k++) {
            const ulonglong2* ar = reinterpret_cast<const ulonglong2*>(&Asd[k][0]);
            ulonglong2 a01 = ar[ty * 2 + 0];
            ulonglong2 a23 = ar[ty * 2 + 1];
            const ulonglong2* br = reinterpret_cast<const ulonglong2*>(&Bs[k][0]);
#pragma unroll
            for (int i = 0; i < 4; i++) {
                ulonglong2 q = br[tx * 4 + i];
                fma2(acc[0][2 * i + 0], a01.x, q.x);
                fma2(acc[0][2 * i + 1], a01.x, q.y);
                fma2(acc[1][2 * i + 0], a01.y, q.x);
                fma2(acc[1][2 * i + 1], a01.y, q.y);
                fma2(acc[2][2 * i + 0], a23.x, q.x);
                fma2(acc[2][2 * i + 1], a23.x, q.y);
                fma2(acc[3][2 * i + 0], a23.y, q.x);
                fma2(acc[3][2 * i + 1], a23.y, q.y);
            }
        }
        __syncthreads();
    }

#pragma unroll
    for (int i = 0; i < 4; i++) {
        int m = m0 + ty * 4 + i;
        int crow = (MODE == 1) ? ((m & 15) * Tc + (m >> 4)) : m;
        float* Cr = C + (size_t)crow * ldc;
#pragma unroll
        for (int p = 0; p < 8; p++) {
            int n = n0 + tx * 16 + 2 * p;
            if (n < N) {
                float2 v = up2(acc[i][p]);
                float r0 = v.x + bias[n], r1 = v.y + bias[n + 1];
                if (ACT) { r0 = tanhf(r0); r1 = tanhf(r1); }
                *reinterpret_cast<float2*>(Cr + n) = make_float2(r0, r1);
            }
        }
    }
}

// ---------------- bz = b_red @ Wx + b_lstm ---------------------------------
__global__ void bz_k(const float* __restrict__ b_red, const float* __restrict__ Wx,
                     const float* __restrict__ b_lstm)
{
    int j = threadIdx.x;
    float s = b_lstm[j];
    for (int e = 0; e < Ec; e++) s += b_red[e] * Wx[e * 1024 + j];
    g_bz[j] = s;
}

// ---------------- pack W2 slices -------------------------------------------
__global__ void pack_k(const float* __restrict__ Wh)
{
    int blk = blockIdx.x;
    int r = blk >> 9, k = blk & 511;
    int q = threadIdx.x;
    int g = q >> 5, j = q & 31;
    int col = g * 256 + r * 32 + j;
    float v = (k < 256) ? g_A2[k * 1024 + col] : Wh[(size_t)(k - 256) * 1024 + col];
    g_W2p[((size_t)(r * 512 + k)) * 128 + q] = v;
}

// ---------------- pack A' (bf16 hi|hi|lo) ----------------------------------
__global__ void packA_k()
{
    int m = blockIdx.x;           // 0..MPAD-1
    int k = threadIdx.x;          // 0..255
    float v = (m < MALL) ? g_feat[m * 256 + k] : 0.f;
    __nv_bfloat16 hi = __float2bfloat16(v);
    __nv_bfloat16 lo = __float2bfloat16(v - __bfloat162float(hi));
    unsigned short uh = __bfloat16_as_ushort(hi), ul = __bfloat16_as_ushort(lo);
    g_Abf[(size_t)m * KBF + k]       = uh;
    g_Abf[(size_t)m * KBF + 256 + k] = uh;
    g_Abf[(size_t)m * KBF + 512 + k] = ul;
}

// ---------------- pack+transpose B' (bf16 hi;lo;hi), vectorized stores ------
__global__ void __launch_bounds__(256) packB_k(const float* __restrict__ W_out)
{
    __shared__ float tile[256][33];      // 256 k x 32 n (+1 pad)
    int n0 = blockIdx.x * 32;
    int t = threadIdx.x;
#pragma unroll
    for (int i = 0; i < 8; i++) {
        int idx = i * 256 + t;           // 0..2047
        int k = idx >> 3, nq = idx & 7;
        int n = n0 + nq * 4;
        float4 v = (n < Vc) ? *reinterpret_cast<const float4*>(W_out + (size_t)k * Vc + n)
                            : make_float4(0.f, 0.f, 0.f, 0.f);
        tile[k][nq * 4 + 0] = v.x;
        tile[k][nq * 4 + 1] = v.y;
        tile[k][nq * 4 + 2] = v.z;
        tile[k][nq * 4 + 3] = v.w;
    }
    __syncthreads();

    int nl = t & 31;                     // lane -> distinct n (conflict-free LDS)
    int k0 = (t >> 5) * 32;              // 8 k-groups of 32
    unsigned short hibuf[32], lobuf[32];
#pragma unroll
    for (int k = 0; k < 32; k++) {
        float v = tile[k0 + k][nl];
        __nv_bfloat16 hi = __float2bfloat16(v);
        __nv_bfloat16 lo = __float2bfloat16(v - __bfloat162float(hi));
        hibuf[k] = __bfloat16_as_ushort(hi);
        lobuf[k] = __bfloat16_as_ushort(lo);
    }
    size_t base = (size_t)(n0 + nl) * KBF;
    uint4* dhi  = reinterpret_cast<uint4*>(g_Bbf + base + k0);
    uint4* dlo  = reinterpret_cast<uint4*>(g_Bbf + base + 256 + k0);
    uint4* dhi2 = reinterpret_cast<uint4*>(g_Bbf + base + 512 + k0);
    const uint4* sh = reinterpret_cast<const uint4*>(hibuf);
    const uint4* sl = reinterpret_cast<const uint4*>(lobuf);
#pragma unroll
    for (int i = 0; i < 4; i++) { dhi[i] = sh[i]; dhi2[i] = sh[i]; dlo[i] = sl[i]; }
}

// ---------------- mma.sync output GEMM: 128x128 tile, K=768 ----------------
__global__ void __launch_bounds__(256, 2) mma_gemm_k(const float* __restrict__ bias,
                                                     float* __restrict__ out)
{
    __shared__ __align__(16) unsigned short As[2][128 * ROWH];
    __shared__ __align__(16) unsigned short Bs[2][128 * ROWH];

    int tid = threadIdx.x;
    int lane = tid & 31, w = tid >> 5;
    int wm = w & 1, wn = w >> 1;                 // warp grid 2(m) x 4(n)
    int m0 = blockIdx.x * 128;                   // x = m-tile (13) — fastest
    int n0 = blockIdx.y * 128;                   // y = n-tile (392)

    const unsigned short* Ag = g_Abf + (size_t)m0 * KBF;
    const unsigned short* Bg = g_Bbf + (size_t)n0 * KBF;

    unsigned sA[2] = { s2u(&As[0][0]), s2u(&As[1][0]) };
    unsigned sB[2] = { s2u(&Bs[0][0]), s2u(&Bs[1][0]) };

    int lrow = tid >> 2, lj = tid & 3;           // loader: 64 rows x 4 x 16B

    float acc[4][4][4];
#pragma unroll
    for (int a = 0; a < 4; a++)
#pragma unroll
        for (int b = 0; b < 4; b++)
#pragma unroll
            for (int c = 0; c < 4; c++) acc[a][b][c] = 0.f;

    // ldmatrix per-lane offsets (element units)
    int a_m = wm * 64 + (lane & 15);
    int a_k = (lane >> 4) * 8;
    int b_n = wn * 32 + (lane & 7) + ((lane >> 4) << 3);
    int b_k = ((lane >> 3) & 1) * 8;

#define LOADC(c, buf) do { \
        const unsigned short* Asrc = Ag + (c) * BKC + (size_t)lrow * KBF + lj * 8; \
        const unsigned short* Bsrc = Bg + (c) * BKC + (size_t)lrow * KBF + lj * 8; \
        cp16(sA[buf] + (lrow * ROWH + lj * 8) * 2, Asrc); \
        cp16(sA[buf] + ((lrow + 64) * ROWH + lj * 8) * 2, Asrc + (size_t)64 * KBF); \
        cp16(sB[buf] + (lrow * ROWH + lj * 8) * 2, Bsrc); \
        cp16(sB[buf] + ((lrow + 64) * ROWH + lj * 8) * 2, Bsrc + (size_t)64 * KBF); \
        CP_COMMIT(); \
    } while (0)

    LOADC(0, 0);

    for (int c = 0; c < NCH; c++) {
        int buf = c & 1;
        CP_WAIT0();
        __syncthreads();
        if (c + 1 < NCH) LOADC(c + 1, buf ^ 1);

#pragma unroll
        for (int ks = 0; ks < 2; ks++) {
            unsigned af[4][4];
#pragma unroll
            for (int mt = 0; mt < 4; mt++) {
                unsigned addr = sA[buf] + ((a_m + mt * 16) * ROWH + ks * 16 + a_k) * 2;
                asm volatile("ldmatrix.sync.aligned.m8n8.x4.shared.b16 {%0,%1,%2,%3}, [%4];"
                    : "=r"(af[mt][0]), "=r"(af[mt][1]), "=r"(af[mt][2]), "=r"(af[mt][3])
                    : "r"(addr));
            }
            unsigned bf[2][4];
#pragma unroll
            for (int np = 0; np < 2; np++) {
                unsigned addr = sB[buf] + ((b_n + np * 16) * ROWH + ks * 16 + b_k) * 2;
                asm volatile("ldmatrix.sync.aligned.m8n8.x4.shared.b16 {%0,%1,%2,%3}, [%4];"
                    : "=r"(bf[np][0]), "=r"(bf[np][1]), "=r"(bf[np][2]), "=r"(bf[np][3])
                    : "r"(addr));
            }
#pragma unroll
            for (int mt = 0; mt < 4; mt++)
#pragma unroll
                for (int nt = 0; nt < 4; nt++) {
                    unsigned bb0 = bf[nt >> 1][(nt & 1) * 2 + 0];
                    unsigned bb1 = bf[nt >> 1][(nt & 1) * 2 + 1];
                    asm volatile(
                        "mma.sync.aligned.m16n8k16.row.col.f32.bf16.bf16.f32 "
                        "{%0,%1,%2,%3}, {%4,%5,%6,%7}, {%8,%9}, {%0,%1,%2,%3};"
                        : "+f"(acc[mt][nt][0]), "+f"(acc[mt][nt][1]),
                          "+f"(acc[mt][nt][2]), "+f"(acc[mt][nt][3])
                        : "r"(af[mt][0]), "r"(af[mt][1]), "r"(af[mt][2]), "r"(af[mt][3]),
                          "r"(bb0), "r"(bb1));
                }
        }
        __syncthreads();
    }
#undef LOADC

    // epilogue: direct stores (32B contiguous per 4-lane group), bias fused
    int g = lane >> 2, T = lane & 3;
#pragma unroll
    for (int mt = 0; mt < 4; mt++) {
        int mrow0 = m0 + wm * 64 + mt * 16 + g;
#pragma unroll
        for (int half = 0; half < 2; half++) {
            int m = mrow0 + half * 8;
            if (m < MALL) {
                int crow = (m & 15) * Tc + (m >> 4);
                float* orow = out + (size_t)crow * EXTV;
#pragma unroll
                for (int nt = 0; nt < 4; nt++) {
                    int col = n0 + wn * 32 + nt * 8 + T * 2;
                    if (col < Vc) {
                        float2 bv = *reinterpret_cast<const float2*>(bias + col);
                        float2 v;
                        v.x = acc[mt][nt][half * 2 + 0] + bv.x;
                        v.y = acc[mt][nt][half * 2 + 1] + bv.y;
                        *reinterpret_cast<float2*>(orow + col) = v;
                    }
                }
            }
        }
    }
}

// ---------------- per-batch bitonic sort of extended ids -------------------
__global__ void sort_k(const int* __restrict__ ext_src)
{
    __shared__ int key[512];
    int b = blockIdx.x, tid = threadIdx.x;
    key[tid] = (tid < Sc) ? (ext_src[b * Sc + tid] * 512 + tid) : 0x7FFFFFFF;
    __syncthreads();
    for (int k = 2; k <= 512; k <<= 1)
        for (int j = k >> 1; j > 0; j >>= 1) {
            int ixj = tid ^ j;
            if (ixj > tid) {
                int a = key[tid], c = key[ixj];
                bool up = ((tid & k) == 0);
                if ((a > c) == up) { key[tid] = c; key[ixj] = a; }
            }
            __syncthreads();
        }
    g_skey[b * 512 + tid] = key[tid];
}

// ---------------- recurrence: 8-CTA cluster per batch element --------------
// 2 cluster syncs / step; 384/512 weight rows resident in SMEM (flush-proof)
__global__ void __launch_bounds__(256) __cluster_dims__(8, 1, 1)
recur_k(const float* __restrict__ init_h, const float* __restrict__ init_c,
        const int* __restrict__ enc_mask)
{
    extern __shared__ __align__(16) float smw[];   // [KSM][128] weights
    __shared__ __align__(16) float svec[2][512];
    __shared__ float sc[32];
    __shared__ __align__(16) ull zp[8][32][2];
    __shared__ float z[128];
    __shared__ float se[56];
    __shared__ float w_sm[56];
    __shared__ __align__(8) float2 sstat[8];
    __shared__ __align__(16) float pbuf[8][256];
    __shared__ int smask[56];

    int tid = threadIdx.x;
    unsigned r; asm("mov.u32 %0, %%cluster_ctarank;" : "=r"(r));
    int b = blockIdx.x >> 3;
    int lane = tid & 31, warp = tid >> 5;

    const float* wbase0 = g_W2p + (size_t)r * 512 * 128;

    // stage first KSM weight rows into smem (reused 100 steps; immune to L1 flush)
    {
        const float4* src = reinterpret_cast<const float4*>(wbase0);
        float4* dst = reinterpret_cast<float4*>(smw);
        for (int i = tid; i < KSM * 32; i += 256) dst[i] = src[i];
    }
    for (int i = tid; i < 256; i += 256) {
        svec[0][i] = 0.f;
        svec[0][256 + i] = init_h[b * 256 + i];
    }
    if (tid < 32) sc[tid] = init_c[b * 256 + r * 32 + tid];
    if (tid < 50) smask[tid] = enc_mask[b * 400 + r * 50 + tid];
    __syncthreads();
    CLUSTER_SYNC();

    const float* memB = g_mem + ((size_t)b * 400 + r * 50) * 256;

    for (int t = 0; t < 100; t++) {
        int cur = t & 1, nxt = cur ^ 1;

        // ---- z slice: [ctx|h] @ W2p[r]; warps 0-5 smem, warps 6-7 stream L2 ----
        {
            int cp = tid & 31, kq = tid >> 5;
            const float* sv = &svec[cur][kq * 64];
            ull a0 = 0ull, a1 = 0ull;
            if (kq < 6) {
                const float* wp = smw + (size_t)(kq * 64) * 128 + cp * 4;
#pragma unroll 8
                for (int k = 0; k < 64; k++) {
                    const ull* w2 = reinterpret_cast<const ull*>(wp);
                    ull s = dup2(sv[k]);
                    fma2(a0, s, w2[0]);
                    fma2(a1, s, w2[1]);
                    wp += 128;
                }
            } else {
                const float* wp = wbase0 + (size_t)(kq * 64) * 128 + cp * 4;
#pragma unroll 8
                for (int k = 0; k < 64; k++) {
                    const ull* w2 = reinterpret_cast<const ull*>(wp);
                    ull s = dup2(sv[k]);
                    fma2(a0, s, w2[0]);
                    fma2(a1, s, w2[1]);
                    wp += 128;
                }
            }
            zp[kq][cp][0] = a0;
            zp[kq][cp][1] = a1;
        }
        __syncthreads();
        if (tid < 64) {
            int cp = tid >> 1, hf = tid & 1;
            ull s = zp[0][cp][hf];
#pragma unroll
            for (int q = 1; q < 8; q++) s = add2(s, zp[q][cp][hf]);
            float2 v = up2(s);
            int q0 = tid * 2, g = q0 >> 5;
            int col = g * 256 + (int)r * 32 + (q0 & 31);
            float2 zev = *reinterpret_cast<const float2*>(
                g_ze + (size_t)(t * 16 + b) * 1024 + col);
            z[q0] = v.x + zev.x;
            z[q0 + 1] = v.y + zev.y;
        }
        __syncthreads();

        // ---- LSTM gates for own 32 lanes; push paired h to all ranks ----
        if (tid < 32) {
            int j = tid;
            float zi = z[j], zf = z[32 + j], zg = z[64 + j], zo = z[96 + j];
            float c = sigm(zf) * sc[j] + sigm(zi) * tanhf(zg);
            sc[j] = c;
            float h = sigm(zo) * tanhf(c);
            float hn = __shfl_down_sync(~0u, h, 1);
            if (!(j & 1)) {
                unsigned dst = s2u(&svec[nxt][256 + r * 32 + j]);
#pragma unroll
                for (unsigned q = 0; q < 8; q++) stc_f2(dst, q, make_float2(h, hn));
            }
        }
        CLUSTER_SYNC();   // #1: new h complete in every CTA

        // ---- energy over own 50 rows (uses NEW h) ----
        {
            const float* hN = &svec[nxt][256];
            for (int so = warp; so < 50; so += 8) {
                const float* mr = memB + (size_t)so * 256 + lane * 8;
                float4 m0 = *reinterpret_cast<const float4*>(mr);
                float4 m1 = *reinterpret_cast<const float4*>(mr + 4);
                float4 h0 = *reinterpret_cast<const float4*>(hN + lane * 8);
                float4 h1 = *reinterpret_cast<const float4*>(hN + lane * 8 + 4);
                float a = m0.x * h0.x + m0.y * h0.y + m0.z * h0.z + m0.w * h0.w
                        + m1.x * h1.x + m1.y * h1.y + m1.z * h1.z + m1.w * h1.w;
#pragma unroll
                for (int o = 16; o; o >>= 1) a += __shfl_xor_sync(~0u, a, o);
                if (lane == 0) {
                    float e = smask[so] ? a : NEGV;
                    se[so] = e;
                    g_energy[(size_t)(t * 16 + b) * 400 + r * 50 + so] = e;
                }
            }
        }
        __syncthreads();

        // ---- local stats + exp-weights (one pass, warp0) ----
        float m_r = 0.f, s_r = 0.f;
        if (warp == 0) {
            float v1 = (lane < 50) ? se[lane] : NEGV;
            float v2 = (lane + 32 < 50) ? se[lane + 32] : NEGV;
            float m = fmaxf(v1, v2);
#pragma unroll
            for (int o = 16; o; o >>= 1) m = fmaxf(m, __shfl_xor_sync(~0u, m, o));
            float e1 = (lane < 50) ? expf(v1 - m) : 0.f;
            float e2 = (lane + 32 < 50) ? expf(v2 - m) : 0.f;
            if (lane < 50) w_sm[lane] = e1;
            if (lane + 32 < 50) w_sm[lane + 32] = e2;
            float s = e1 + e2;
#pragma unroll
            for (int o = 16; o; o >>= 1) s += __shfl_xor_sync(~0u, s, o);
            m_r = m; s_r = s;
        }
        __syncthreads();

        // ---- unnormalized partial ctx; paired push + stats together ----
        {
            float p = 0.f;
            const float* mc = memB + tid;
#pragma unroll 10
            for (int so = 0; so < 50; so++) p += w_sm[so] * mc[(size_t)so * 256];
            float pn = __shfl_down_sync(~0u, p, 1);
            if (!(tid & 1)) {
                unsigned dst = s2u(&pbuf[r][tid]);
#pragma unroll
                for (unsigned q = 0; q < 8; q++) stc_f2(dst, q, make_float2(p, pn));
            }
        }
        if (warp == 0 && lane == 0) {
            unsigned dst = s2u(&sstat[r]);
#pragma unroll
            for (unsigned q = 0; q < 8; q++) stc_f2(dst, q, make_float2(m_r, s_r));
        }
        CLUSTER_SYNC();   // #2: partial ctx + stats complete

        // ---- merge: global softmax rescale, full ctx locally ----
        {
            float gm = NEGV;
#pragma unroll
            for (int q = 0; q < 8; q++) gm = fmaxf(gm, sstat[q].x);
            float gs = 0.f, nc = 0.f;
#pragma unroll
            for (int q = 0; q < 8; q++) {
                float wq = expf(sstat[q].x - gm);
                gs += wq * sstat[q].y;
                nc += wq * pbuf[q][tid];
            }
            svec[nxt][tid] = nc / gs;
        }
        __syncthreads();

        // ---- stash own slice of [h | ctx] for epilogue GEMMs ----
        if (tid < 64) {
            int j = tid & 31;
            float* cr = g_cat + (size_t)(t * 16 + b) * 512;
            if (tid < 32) cr[r * 32 + j] = svec[nxt][256 + r * 32 + j];
            else          cr[256 + r * 32 + j] = svec[nxt][r * 32 + j];
        }
    }
}

// ---------------- zero the OOV logit region (float4) -----------------------
__global__ void zoov_k(float* __restrict__ out)
{
    int r = blockIdx.x;
    int v = threadIdx.x;
    if (v < 250)
        *reinterpret_cast<float4*>(out + (size_t)r * EXTV + Vc + v * 4) =
            make_float4(0.f, 0.f, 0.f, 0.f);
}

// ---------------- pointer-generator copy scatter ---------------------------
__global__ void scatter_k(float* __restrict__ out)
{
    __shared__ float se[Sc];
    __shared__ int sk[Sc];
    int bt = blockIdx.x;
    int b = bt / Tc, t = bt % Tc;
    int tid = threadIdx.x;
    if (tid < Sc) {
        se[tid] = g_energy[(size_t)(t * Bc + b) * Sc + tid];
        sk[tid] = g_skey[b * 512 + tid];
    }
    __syncthreads();
    if (tid < Sc) {
        int k = sk[tid], id = k >> 9;
        bool start = (tid == 0) || ((sk[tid - 1] >> 9) != id);
        if (start) {
            float m = se[k & 511];
            int j = tid + 1;
            while (j < Sc && (sk[j] >> 9) == id) {
                m = fmaxf(m, se[sk[j] & 511]);
                j++;
            }
            if (m > NEGV * 0.5f) out[(size_t)bt * EXTV + id] += m;
        }
    }
}

// ---------------- launch ----------------------------------------------------
extern "C" void kernel_launch(void* const* d_in, const int* in_sizes, int n_in,
                              void* d_out, int out_size)
{
    const int*   trg      = (const int*)d_in[0];
    const int*   ext_src  = (const int*)d_in[1];
    const int*   enc_mask = (const int*)d_in[2];
    const float* enc_out  = (const float*)d_in[3];
    const float* init_h   = (const float*)d_in[4];
    const float* init_c   = (const float*)d_in[5];
    const float* emb      = (const float*)d_in[6];
    const float* W_enc    = (const float*)d_in[7];
    const float* b_enc    = (const float*)d_in[8];
    const float* W_red    = (const float*)d_in[9];
    const float* b_red    = (const float*)d_in[10];
    const float* Wx       = (const float*)d_in[11];
    const float* Wh       = (const float*)d_in[12];
    const float* b_lstm   = (const float*)d_in[13];
    const float* W_cat    = (const float*)d_in[14];
    const float* b_cat    = (const float*)d_in[15];
    const float* W_out    = (const float*)d_in[16];
    const float* b_out    = (const float*)d_in[17];
    float* out = (float*)d_out;

    void* p;
    cudaGetSymbolAddress(&p, g_mem);  float* pMem  = (float*)p;
    cudaGetSymbolAddress(&p, g_A1);   float* pA1   = (float*)p;
    cudaGetSymbolAddress(&p, g_A2);   float* pA2   = (float*)p;
    cudaGetSymbolAddress(&p, g_bz);   float* pBz   = (float*)p;
    cudaGetSymbolAddress(&p, g_ze);   float* pZe   = (float*)p;
    cudaGetSymbolAddress(&p, g_cat);  float* pCat  = (float*)p;
    cudaGetSymbolAddress(&p, g_feat); float* pFeat = (float*)p;

    cudaFuncSetAttribute(recur_k, cudaFuncAttributeMaxDynamicSharedMemorySize, SMW_BYTES);

    // 1) bz = b_red @ Wx + b_lstm
    bz_k<<<1, 1024>>>(b_red, Wx, b_lstm);
    // 2) B' pack+transpose (only needs W_out)
    packB_k<<<NPAD / 32, 256>>>(W_out);
    // 3) A1 = Wr_top @ Wx;  A2 = Wr_bot @ Wx
    gemm_k<0, 0, false><<<dim3(8, 2), 256>>>(W_red, Wx, nullptr, pA1,
                                             128, 1024, 128, 128, 1024, nullptr);
    gemm_k<0, 0, false><<<dim3(8, 4), 256>>>(W_red + 128 * 128, Wx, nullptr, pA2,
                                             256, 1024, 128, 128, 1024, nullptr);
    // 4) ze = emb[trg] @ A1 + bz
    gemm_k<0, 0, true><<<dim3(8, 25), 256>>>(emb, pA1, pBz, pZe,
                                             1600, 1024, 128, 128, 1024, trg);
    // 5) memories = encoder_outputs @ W_enc + b_enc
    gemm2_k<0, 0><<<dim3(1, 100), 256>>>(enc_out, W_enc, b_enc, pMem,
                                         6400, 256, 256, 256, 256);
    // 6) pack W2 slices
    pack_k<<<8 * 512, 128>>>(Wh);
    // 7) per-batch id sort
    sort_k<<<16, 512>>>(ext_src);
    // 8) clustered recurrence (weights in smem)
    recur_k<<<128, 256, SMW_BYTES>>>(init_h, init_c, enc_mask);
    // 9) feat = tanh(cat @ W_cat + b_cat)
    gemm2_k<1, 0><<<dim3(1, 25), 256>>>(pCat, W_cat, b_cat, pFeat,
                                        1600, 256, 512, 512, 256);
    // 10) A' pack
    packA_k<<<MPAD, 256>>>();
    // 11) zero the OOV region
    zoov_k<<<1600, 256>>>(out);
    // 12) logits via mma.sync bf16 (3-term split, K=768)
    mma_gemm_k<<<dim3(MPAD / 128, NPAD / 128), 256>>>(b_out, out);
    // 13) += scatter-max copy scores
    scatter_k<<<1600, 512>>>(out);
}

// round 15
// speedup vs baseline: 1.6784x; 1.6784x over previous
#include <cuda_runtime.h>
#include <cuda_bf16.h>
#include <cstdint>

typedef unsigned long long ull;

#define NEGV (-1e12f)
constexpr int Bc = 16, Tc = 100, Sc = 400, Vc = 50000, Ec = 128, Hc = 256;
constexpr int EXTV = Vc + 1000;
constexpr int MALL = Bc * Tc;   // 1600
constexpr int MPAD = 1664;      // 13 * 128
constexpr int NPAD = 50176;     // 392 * 128
constexpr int KBF  = 768;       // 3 * 256 (bf16 hi/lo split)
constexpr int BKC  = 32;        // K per chunk in mma kernel
constexpr int NCH  = KBF / BKC; // 24
constexpr int ROWH = 40;        // smem halves per row (80B, conflict-free ldmatrix)

// ---------------- scratch (static device globals; no allocations) ----------
__device__ __align__(16) float g_mem[Bc * Sc * Hc];
__device__ __align__(16) float g_A1[Ec * 4 * Hc];
__device__ __align__(16) float g_A2[Hc * 4 * Hc];
__device__ __align__(16) float g_W2p[8 * 512 * 128];
__device__ __align__(16) float g_bz[4 * Hc];
__device__ __align__(16) float g_ze[MALL * 4 * Hc];
__device__ __align__(16) float g_energy[Tc * Bc * Sc];
__device__ __align__(16) float g_cat[MALL * 2 * Hc];
__device__ __align__(16) float g_feat[MALL * Hc];
__device__ int g_skey[Bc * 512];
__device__ __align__(16) unsigned short g_Abf[MPAD * KBF];         // A' bf16
__device__ __align__(16) unsigned short g_Bbf[(size_t)NPAD * KBF]; // B' bf16 (77MB)

// ---------------- f32x2 helpers --------------------------------------------
__device__ __forceinline__ ull dup2(float a) {
    ull r; asm("mov.b64 %0, {%1,%1};" : "=l"(r) : "f"(a)); return r;
}
__device__ __forceinline__ void fma2(ull& d, ull a, ull b) {
    asm("fma.rn.f32x2 %0, %1, %2, %0;" : "+l"(d) : "l"(a), "l"(b));
}
__device__ __forceinline__ ull add2(ull a, ull b) {
    ull r; asm("add.rn.f32x2 %0, %1, %2;" : "=l"(r) : "l"(a), "l"(b)); return r;
}
__device__ __forceinline__ float2 up2(ull v) {
    float2 r; asm("mov.b64 {%0,%1}, %2;" : "=f"(r.x), "=f"(r.y) : "l"(v)); return r;
}
__device__ __forceinline__ float sigm(float x) { return 1.f / (1.f + expf(-x)); }

// ---------------- DSMEM / cluster helpers ----------------------------------
__device__ __forceinline__ unsigned s2u(const void* p) {
    return (unsigned)__cvta_generic_to_shared(p);
}
__device__ __forceinline__ void stc_f(unsigned laddr, unsigned rank, float v) {
    unsigned ra;
    asm volatile("mapa.shared::cluster.u32 %0, %1, %2;" : "=r"(ra) : "r"(laddr), "r"(rank));
    asm volatile("st.shared::cluster.f32 [%0], %1;" :: "r"(ra), "f"(v));
}
__device__ __forceinline__ void stc_f2(unsigned laddr, unsigned rank, float2 v) {
    unsigned ra;
    asm volatile("mapa.shared::cluster.u32 %0, %1, %2;" : "=r"(ra) : "r"(laddr), "r"(rank));
    asm volatile("st.shared::cluster.v2.f32 [%0], {%1,%2};" :: "r"(ra), "f"(v.x), "f"(v.y));
}
#define CLUSTER_SYNC() do { \
    asm volatile("barrier.cluster.arrive.aligned;" ::: "memory"); \
    asm volatile("barrier.cluster.wait.aligned;"   ::: "memory"); } while (0)

// ---------------- cp.async helpers -----------------------------------------
__device__ __forceinline__ void cp16(unsigned d, const void* s) {
    asm volatile("cp.async.cg.shared.global [%0], [%1], 16;" :: "r"(d), "l"(s));
}
#define CP_COMMIT() asm volatile("cp.async.commit_group;" ::: "memory")
#define CP_WAIT0()  asm volatile("cp.async.wait_group 0;" ::: "memory")

// ---------------- generic GEMM (A1/A2/ze) ----------------------------------
template <int ACT, int MODE, bool GATHER>
__global__ void __launch_bounds__(256) gemm_k(
    const float* __restrict__ A, const float* __restrict__ W,
    const float* __restrict__ bias, float* __restrict__ C,
    int M, int N, int K, int lda, int ldc, const int* __restrict__ gidx)
{
    __shared__ __align__(16) float As[32][68];
    __shared__ __align__(16) float Bs[32][128];
    int tid = threadIdx.x;
    int n0 = blockIdx.x * 128;
    int m0 = blockIdx.y * 64;
    int tx = tid & 15, ty = tid >> 4;

    int arw = tid >> 2;
    int amr = m0 + arw;
    const float* Arow;
    if (GATHER) {
        int g = gidx[(amr & 15) * Tc + (amr >> 4)];
        Arow = A + (size_t)g * lda;
    } else {
        Arow = A + (size_t)amr * lda;
    }
    int akk = (tid & 3) * 8;
    int bk = tid >> 3;
    int bn = (tid & 7) * 16;

    ull acc[4][4];
#pragma unroll
    for (int i = 0; i < 4; i++)
#pragma unroll
        for (int p = 0; p < 4; p++) acc[i][p] = 0ull;

    int nch = K >> 5;
    for (int kc = 0; kc < nch; kc++) {
        float4 a0 = *reinterpret_cast<const float4*>(Arow + kc * 32 + akk);
        float4 a1 = *reinterpret_cast<const float4*>(Arow + kc * 32 + akk + 4);
        As[akk + 0][arw] = a0.x; As[akk + 1][arw] = a0.y;
        As[akk + 2][arw] = a0.z; As[akk + 3][arw] = a0.w;
        As[akk + 4][arw] = a1.x; As[akk + 5][arw] = a1.y;
        As[akk + 6][arw] = a1.z; As[akk + 7][arw] = a1.w;

        const float* Wrow = W + (size_t)(kc * 32 + bk) * N + n0 + bn;
#pragma unroll
        for (int i = 0; i < 4; i++) {
            int n = n0 + bn + 4 * i;
            float4 v = (n < N) ? *reinterpret_cast<const float4*>(Wrow + 4 * i)
                               : make_float4(0.f, 0.f, 0.f, 0.f);
            *reinterpret_cast<float4*>(&Bs[bk][bn + 4 * i]) = v;
        }
        __syncthreads();

#pragma unroll
        for (int k = 0; k < 32; k++) {
            const ull* brow = reinterpret_cast<const ull*>(&Bs[k][0]);
            ull b0 = brow[tx * 4 + 0], b1 = brow[tx * 4 + 1];
            ull b2 = brow[tx * 4 + 2], b3 = brow[tx * 4 + 3];
#pragma unroll
            for (int i = 0; i < 4; i++) {
                ull a2 = dup2(As[k][ty * 4 + i]);
                fma2(acc[i][0], a2, b0);
                fma2(acc[i][1], a2, b1);
                fma2(acc[i][2], a2, b2);
                fma2(acc[i][3], a2, b3);
            }
        }
        __syncthreads();
    }

#pragma unroll
    for (int i = 0; i < 4; i++) {
        int m = m0 + ty * 4 + i;
        int crow = (MODE == 1) ? ((m & 15) * Tc + (m >> 4)) : m;
        float* Crow = C + (size_t)crow * ldc;
#pragma unroll
        for (int p = 0; p < 4; p++) {
            int n = n0 + tx * 8 + 2 * p;
            if (n < N) {
                float2 v = up2(acc[i][p]);
                float r0 = v.x, r1 = v.y;
                if (bias) { r0 += bias[n]; r1 += bias[n + 1]; }
                if (ACT) { r0 = tanhf(r0); r1 = tanhf(r1); }
                Crow[n] = r0;
                Crow[n + 1] = r1;
            }
        }
    }
}

// ---------------- fast fp32 GEMM (memories / feat) -------------------------
template <int ACT, int MODE>
__global__ void __launch_bounds__(256, 2) gemm2_k(
    const float* __restrict__ A, const float* __restrict__ W,
    const float* __restrict__ bias, float* __restrict__ C,
    int M, int N, int K, int lda, int ldc)
{
    __shared__ __align__(16) ull   Asd[16][64];
    __shared__ __align__(16) float Bs[16][256];
    int tid = threadIdx.x;
    int n0 = blockIdx.x * 256, m0 = blockIdx.y * 64;
    int tx = tid & 15, ty = tid >> 4;

    int arow = tid >> 2;
    int akq = (tid & 3) * 4;
    const float* Ap = A + (size_t)(m0 + arow) * lda + akq;

    ull acc[4][8];
#pragma unroll
    for (int i = 0; i < 4; i++)
#pragma unroll
        for (int p = 0; p < 8; p++) acc[i][p] = 0ull;

    for (int kc = 0; kc < K; kc += 16) {
        float4 av = *reinterpret_cast<const float4*>(Ap);
        Ap += 16;
        Asd[akq + 0][arow] = dup2(av.x);
        Asd[akq + 1][arow] = dup2(av.y);
        Asd[akq + 2][arow] = dup2(av.z);
        Asd[akq + 3][arow] = dup2(av.w);
#pragma unroll
        for (int i = 0; i < 4; i++) {
            int e = i * 256 + tid;
            int rk = e >> 6, cc = (e & 63) * 4;
            int n = n0 + cc;
            float4 v = (n < N) ? *reinterpret_cast<const float4*>(W + (size_t)(kc + rk) * N + n)
                               : make_float4(0.f, 0.f, 0.f, 0.f);
            *reinterpret_cast<float4*>(&Bs[rk][cc]) = v;
        }
        __syncthreads();

#pragma unroll
        for (int k = 0; k < 16; k++) {
            const ulonglong2* ar = reinterpret_cast<const ulonglong2*>(&Asd[k][0]);
            ulonglong2 a01 = ar[ty * 2 + 0];
            ulonglong2 a23 = ar[ty * 2 + 1];
            const ulonglong2* br = reinterpret_cast<const ulonglong2*>(&Bs[k][0]);
#pragma unroll
            for (int i = 0; i < 4; i++) {
                ulonglong2 q = br[tx * 4 + i];
                fma2(acc[0][2 * i + 0], a01.x, q.x);
                fma2(acc[0][2 * i + 1], a01.x, q.y);
                fma2(acc[1][2 * i + 0], a01.y, q.x);
                fma2(acc[1][2 * i + 1], a01.y, q.y);
                fma2(acc[2][2 * i + 0], a23.x, q.x);
                fma2(acc[2][2 * i + 1], a23.x, q.y);
                fma2(acc[3][2 * i + 0], a23.y, q.x);
                fma2(acc[3][2 * i + 1], a23.y, q.y);
            }
        }
        __syncthreads();
    }

#pragma unroll
    for (int i = 0; i < 4; i++) {
        int m = m0 + ty * 4 + i;
        int crow = (MODE == 1) ? ((m & 15) * Tc + (m >> 4)) : m;
        float* Cr = C + (size_t)crow * ldc;
#pragma unroll
        for (int p = 0; p < 8; p++) {
            int n = n0 + tx * 16 + 2 * p;
            if (n < N) {
                float2 v = up2(acc[i][p]);
                float r0 = v.x + bias[n], r1 = v.y + bias[n + 1];
                if (ACT) { r0 = tanhf(r0); r1 = tanhf(r1); }
                *reinterpret_cast<float2*>(Cr + n) = make_float2(r0, r1);
            }
        }
    }
}

// ---------------- bz = b_red @ Wx + b_lstm ---------------------------------
__global__ void bz_k(const float* __restrict__ b_red, const float* __restrict__ Wx,
                     const float* __restrict__ b_lstm)
{
    int j = threadIdx.x;
    float s = b_lstm[j];
    for (int e = 0; e < Ec; e++) s += b_red[e] * Wx[e * 1024 + j];
    g_bz[j] = s;
}

// ---------------- pack W2 slices -------------------------------------------
__global__ void pack_k(const float* __restrict__ Wh)
{
    int blk = blockIdx.x;
    int r = blk >> 9, k = blk & 511;
    int q = threadIdx.x;
    int g = q >> 5, j = q & 31;
    int col = g * 256 + r * 32 + j;
    float v = (k < 256) ? g_A2[k * 1024 + col] : Wh[(size_t)(k - 256) * 1024 + col];
    g_W2p[((size_t)(r * 512 + k)) * 128 + q] = v;
}

// ---------------- pack A' (bf16 hi|hi|lo) ----------------------------------
__global__ void packA_k()
{
    int m = blockIdx.x;           // 0..MPAD-1
    int k = threadIdx.x;          // 0..255
    float v = (m < MALL) ? g_feat[m * 256 + k] : 0.f;
    __nv_bfloat16 hi = __float2bfloat16(v);
    __nv_bfloat16 lo = __float2bfloat16(v - __bfloat162float(hi));
    unsigned short uh = __bfloat16_as_ushort(hi), ul = __bfloat16_as_ushort(lo);
    g_Abf[(size_t)m * KBF + k]       = uh;
    g_Abf[(size_t)m * KBF + 256 + k] = uh;
    g_Abf[(size_t)m * KBF + 512 + k] = ul;
}

// ---------------- pack+transpose B' (bf16 hi;lo;hi), vectorized stores ------
__global__ void __launch_bounds__(256) packB_k(const float* __restrict__ W_out)
{
    __shared__ float tile[256][33];      // 256 k x 32 n (+1 pad)
    int n0 = blockIdx.x * 32;
    int t = threadIdx.x;
#pragma unroll
    for (int i = 0; i < 8; i++) {
        int idx = i * 256 + t;           // 0..2047
        int k = idx >> 3, nq = idx & 7;
        int n = n0 + nq * 4;
        float4 v = (n < Vc) ? *reinterpret_cast<const float4*>(W_out + (size_t)k * Vc + n)
                            : make_float4(0.f, 0.f, 0.f, 0.f);
        tile[k][nq * 4 + 0] = v.x;
        tile[k][nq * 4 + 1] = v.y;
        tile[k][nq * 4 + 2] = v.z;
        tile[k][nq * 4 + 3] = v.w;
    }
    __syncthreads();

    int nl = t & 31;                     // lane -> distinct n (conflict-free LDS)
    int k0 = (t >> 5) * 32;              // 8 k-groups of 32
    unsigned short hibuf[32], lobuf[32];
#pragma unroll
    for (int k = 0; k < 32; k++) {
        float v = tile[k0 + k][nl];
        __nv_bfloat16 hi = __float2bfloat16(v);
        __nv_bfloat16 lo = __float2bfloat16(v - __bfloat162float(hi));
        hibuf[k] = __bfloat16_as_ushort(hi);
        lobuf[k] = __bfloat16_as_ushort(lo);
    }
    size_t base = (size_t)(n0 + nl) * KBF;
    uint4* dhi  = reinterpret_cast<uint4*>(g_Bbf + base + k0);
    uint4* dlo  = reinterpret_cast<uint4*>(g_Bbf + base + 256 + k0);
    uint4* dhi2 = reinterpret_cast<uint4*>(g_Bbf + base + 512 + k0);
    const uint4* sh = reinterpret_cast<const uint4*>(hibuf);
    const uint4* sl = reinterpret_cast<const uint4*>(lobuf);
#pragma unroll
    for (int i = 0; i < 4; i++) { dhi[i] = sh[i]; dhi2[i] = sh[i]; dlo[i] = sl[i]; }
}

// ---------------- mma.sync output GEMM: 128x128 tile, K=768 ----------------
__global__ void __launch_bounds__(256, 2) mma_gemm_k(const float* __restrict__ bias,
                                                     float* __restrict__ out)
{
    __shared__ __align__(16) unsigned short As[2][128 * ROWH];
    __shared__ __align__(16) unsigned short Bs[2][128 * ROWH];

    int tid = threadIdx.x;
    int lane = tid & 31, w = tid >> 5;
    int wm = w & 1, wn = w >> 1;                 // warp grid 2(m) x 4(n)
    int m0 = blockIdx.x * 128;                   // x = m-tile (13) — fastest
    int n0 = blockIdx.y * 128;                   // y = n-tile (392)

    const unsigned short* Ag = g_Abf + (size_t)m0 * KBF;
    const unsigned short* Bg = g_Bbf + (size_t)n0 * KBF;

    unsigned sA[2] = { s2u(&As[0][0]), s2u(&As[1][0]) };
    unsigned sB[2] = { s2u(&Bs[0][0]), s2u(&Bs[1][0]) };

    int lrow = tid >> 2, lj = tid & 3;           // loader: 64 rows x 4 x 16B

    float acc[4][4][4];
#pragma unroll
    for (int a = 0; a < 4; a++)
#pragma unroll
        for (int b = 0; b < 4; b++)
#pragma unroll
            for (int c = 0; c < 4; c++) acc[a][b][c] = 0.f;

    // ldmatrix per-lane offsets (element units)
    int a_m = wm * 64 + (lane & 15);
    int a_k = (lane >> 4) * 8;
    int b_n = wn * 32 + (lane & 7) + ((lane >> 4) << 3);
    int b_k = ((lane >> 3) & 1) * 8;

#define LOADC(c, buf) do { \
        const unsigned short* Asrc = Ag + (c) * BKC + (size_t)lrow * KBF + lj * 8; \
        const unsigned short* Bsrc = Bg + (c) * BKC + (size_t)lrow * KBF + lj * 8; \
        cp16(sA[buf] + (lrow * ROWH + lj * 8) * 2, Asrc); \
        cp16(sA[buf] + ((lrow + 64) * ROWH + lj * 8) * 2, Asrc + (size_t)64 * KBF); \
        cp16(sB[buf] + (lrow * ROWH + lj * 8) * 2, Bsrc); \
        cp16(sB[buf] + ((lrow + 64) * ROWH + lj * 8) * 2, Bsrc + (size_t)64 * KBF); \
        CP_COMMIT(); \
    } while (0)

    LOADC(0, 0);

    for (int c = 0; c < NCH; c++) {
        int buf = c & 1;
        CP_WAIT0();
        __syncthreads();
        if (c + 1 < NCH) LOADC(c + 1, buf ^ 1);

#pragma unroll
        for (int ks = 0; ks < 2; ks++) {
            unsigned af[4][4];
#pragma unroll
            for (int mt = 0; mt < 4; mt++) {
                unsigned addr = sA[buf] + ((a_m + mt * 16) * ROWH + ks * 16 + a_k) * 2;
                asm volatile("ldmatrix.sync.aligned.m8n8.x4.shared.b16 {%0,%1,%2,%3}, [%4];"
                    : "=r"(af[mt][0]), "=r"(af[mt][1]), "=r"(af[mt][2]), "=r"(af[mt][3])
                    : "r"(addr));
            }
            unsigned bf[2][4];
#pragma unroll
            for (int np = 0; np < 2; np++) {
                unsigned addr = sB[buf] + ((b_n + np * 16) * ROWH + ks * 16 + b_k) * 2;
                asm volatile("ldmatrix.sync.aligned.m8n8.x4.shared.b16 {%0,%1,%2,%3}, [%4];"
                    : "=r"(bf[np][0]), "=r"(bf[np][1]), "=r"(bf[np][2]), "=r"(bf[np][3])
                    : "r"(addr));
            }
#pragma unroll
            for (int mt = 0; mt < 4; mt++)
#pragma unroll
                for (int nt = 0; nt < 4; nt++) {
                    unsigned bb0 = bf[nt >> 1][(nt & 1) * 2 + 0];
                    unsigned bb1 = bf[nt >> 1][(nt & 1) * 2 + 1];
                    asm volatile(
                        "mma.sync.aligned.m16n8k16.row.col.f32.bf16.bf16.f32 "
                        "{%0,%1,%2,%3}, {%4,%5,%6,%7}, {%8,%9}, {%0,%1,%2,%3};"
                        : "+f"(acc[mt][nt][0]), "+f"(acc[mt][nt][1]),
                          "+f"(acc[mt][nt][2]), "+f"(acc[mt][nt][3])
                        : "r"(af[mt][0]), "r"(af[mt][1]), "r"(af[mt][2]), "r"(af[mt][3]),
                          "r"(bb0), "r"(bb1));
                }
        }
        __syncthreads();
    }
#undef LOADC

    // epilogue: direct stores (32B contiguous per 4-lane group), bias fused
    int g = lane >> 2, T = lane & 3;
#pragma unroll
    for (int mt = 0; mt < 4; mt++) {
        int mrow0 = m0 + wm * 64 + mt * 16 + g;
#pragma unroll
        for (int half = 0; half < 2; half++) {
            int m = mrow0 + half * 8;
            if (m < MALL) {
                int crow = (m & 15) * Tc + (m >> 4);
                float* orow = out + (size_t)crow * EXTV;
#pragma unroll
                for (int nt = 0; nt < 4; nt++) {
                    int col = n0 + wn * 32 + nt * 8 + T * 2;
                    if (col < Vc) {
                        float2 bv = *reinterpret_cast<const float2*>(bias + col);
                        float2 v;
                        v.x = acc[mt][nt][half * 2 + 0] + bv.x;
                        v.y = acc[mt][nt][half * 2 + 1] + bv.y;
                        *reinterpret_cast<float2*>(orow + col) = v;
                    }
                }
            }
        }
    }
}

// ---------------- per-batch bitonic sort of extended ids -------------------
__global__ void sort_k(const int* __restrict__ ext_src)
{
    __shared__ int key[512];
    int b = blockIdx.x, tid = threadIdx.x;
    key[tid] = (tid < Sc) ? (ext_src[b * Sc + tid] * 512 + tid) : 0x7FFFFFFF;
    __syncthreads();
    for (int k = 2; k <= 512; k <<= 1)
        for (int j = k >> 1; j > 0; j >>= 1) {
            int ixj = tid ^ j;
            if (ixj > tid) {
                int a = key[tid], c = key[ixj];
                bool up = ((tid & k) == 0);
                if ((a > c) == up) { key[tid] = c; key[ixj] = a; }
            }
            __syncthreads();
        }
    g_skey[b * 512 + tid] = key[tid];
}

// ---------------- recurrence: 8-CTA cluster per batch, 512 threads ---------
// 2 cluster syncs / step; weights stream via L1 (no smem staging)
__global__ void __launch_bounds__(512) __cluster_dims__(8, 1, 1)
recur_k(const float* __restrict__ init_h, const float* __restrict__ init_c,
        const int* __restrict__ enc_mask)
{
    __shared__ __align__(16) float svec[2][512];
    __shared__ float sc[32];
    __shared__ __align__(16) ull zp[16][32][2];
    __shared__ float z[128];
    __shared__ float se[56];
    __shared__ float w_sm[56];
    __shared__ __align__(8) float2 sstat[8];
    __shared__ __align__(16) float pbuf[8][256];
    __shared__ float phalf[256];
    __shared__ int smask[56];

    int tid = threadIdx.x;
    unsigned r; asm("mov.u32 %0, %%cluster_ctarank;" : "=r"(r));
    int b = blockIdx.x >> 3;
    int lane = tid & 31, warp = tid >> 5;

    if (tid < 256) {
        svec[0][tid] = 0.f;
        svec[0][256 + tid] = init_h[b * 256 + tid];
    }
    if (tid < 32) sc[tid] = init_c[b * 256 + r * 32 + tid];
    if (tid < 50) smask[tid] = enc_mask[b * 400 + r * 50 + tid];
    __syncthreads();
    CLUSTER_SYNC();

    const float* wbase0 = g_W2p + (size_t)r * 512 * 128;
    const float* memB = g_mem + ((size_t)b * 400 + r * 50) * 256;

    for (int t = 0; t < 100; t++) {
        int cur = t & 1, nxt = cur ^ 1;

        // ---- z slice: [ctx|h] @ W2p[r]; 16 warps, 32 k-rows each ----
        {
            int cp = tid & 31, kq = tid >> 5;
            const float* wp = wbase0 + (size_t)(kq * 32) * 128 + cp * 4;
            const float* sv = &svec[cur][kq * 32];
            ull a0 = 0ull, a1 = 0ull;
#pragma unroll 8
            for (int k = 0; k < 32; k++) {
                const ull* w2 = reinterpret_cast<const ull*>(wp);
                ull s = dup2(sv[k]);
                fma2(a0, s, w2[0]);
                fma2(a1, s, w2[1]);
                wp += 128;
            }
            zp[kq][cp][0] = a0;
            zp[kq][cp][1] = a1;
        }
        __syncthreads();
        if (tid < 64) {
            int cp = tid >> 1, hf = tid & 1;
            ull s = zp[0][cp][hf];
#pragma unroll
            for (int q = 1; q < 16; q++) s = add2(s, zp[q][cp][hf]);
            float2 v = up2(s);
            int q0 = tid * 2, g = q0 >> 5;
            int col = g * 256 + (int)r * 32 + (q0 & 31);
            float2 zev = *reinterpret_cast<const float2*>(
                g_ze + (size_t)(t * 16 + b) * 1024 + col);
            z[q0] = v.x + zev.x;
            z[q0 + 1] = v.y + zev.y;
        }
        __syncthreads();

        // ---- LSTM gates for own 32 lanes; push paired h to all ranks ----
        if (tid < 32) {
            int j = tid;
            float zi = z[j], zf = z[32 + j], zg = z[64 + j], zo = z[96 + j];
            float c = sigm(zf) * sc[j] + sigm(zi) * tanhf(zg);
            sc[j] = c;
            float h = sigm(zo) * tanhf(c);
            float hn = __shfl_down_sync(~0u, h, 1);
            if (!(j & 1)) {
                unsigned dst = s2u(&svec[nxt][256 + r * 32 + j]);
#pragma unroll
                for (unsigned q = 0; q < 8; q++) stc_f2(dst, q, make_float2(h, hn));
            }
        }
        CLUSTER_SYNC();   // #1: new h complete in every CTA

        // ---- energy over own 50 rows (uses NEW h); 16 warps ----
        {
            const float* hN = &svec[nxt][256];
            for (int so = warp; so < 50; so += 16) {
                const float* mr = memB + (size_t)so * 256 + lane * 8;
                float4 m0 = *reinterpret_cast<const float4*>(mr);
                float4 m1 = *reinterpret_cast<const float4*>(mr + 4);
                float4 h0 = *reinterpret_cast<const float4*>(hN + lane * 8);
                float4 h1 = *reinterpret_cast<const float4*>(hN + lane * 8 + 4);
                float a = m0.x * h0.x + m0.y * h0.y + m0.z * h0.z + m0.w * h0.w
                        + m1.x * h1.x + m1.y * h1.y + m1.z * h1.z + m1.w * h1.w;
#pragma unroll
                for (int o = 16; o; o >>= 1) a += __shfl_xor_sync(~0u, a, o);
                if (lane == 0) {
                    float e = smask[so] ? a : NEGV;
                    se[so] = e;
                    g_energy[(size_t)(t * 16 + b) * 400 + r * 50 + so] = e;
                }
            }
        }
        __syncthreads();

        // ---- local stats + exp-weights (one pass, warp0) ----
        float m_r = 0.f, s_r = 0.f;
        if (warp == 0) {
            float v1 = (lane < 50) ? se[lane] : NEGV;
            float v2 = (lane + 32 < 50) ? se[lane + 32] : NEGV;
            float m = fmaxf(v1, v2);
#pragma unroll
            for (int o = 16; o; o >>= 1) m = fmaxf(m, __shfl_xor_sync(~0u, m, o));
            float e1 = (lane < 50) ? expf(v1 - m) : 0.f;
            float e2 = (lane + 32 < 50) ? expf(v2 - m) : 0.f;
            if (lane < 50) w_sm[lane] = e1;
            if (lane + 32 < 50) w_sm[lane + 32] = e2;
            float s = e1 + e2;
#pragma unroll
            for (int o = 16; o; o >>= 1) s += __shfl_xor_sync(~0u, s, o);
            m_r = m; s_r = s;
        }
        __syncthreads();

        // ---- unnormalized partial ctx over own 50 rows, split 2 halves ----
        {
            int col = tid & 255, half = tid >> 8;
            float p = 0.f;
            const float* mc = memB + (size_t)(half * 25) * 256 + col;
#pragma unroll 5
            for (int so = 0; so < 25; so++) p += w_sm[half * 25 + so] * mc[(size_t)so * 256];
            if (half) phalf[col] = p;
            __syncthreads();
            if (tid < 256) {
                p += phalf[tid];
                float pn = __shfl_down_sync(~0u, p, 1);
                if (!(tid & 1)) {
                    unsigned dst = s2u(&pbuf[r][tid]);
#pragma unroll
                    for (unsigned q = 0; q < 8; q++) stc_f2(dst, q, make_float2(p, pn));
                }
            }
        }
        if (warp == 0 && lane == 0) {
            unsigned dst = s2u(&sstat[r]);
#pragma unroll
            for (unsigned q = 0; q < 8; q++) stc_f2(dst, q, make_float2(m_r, s_r));
        }
        CLUSTER_SYNC();   // #2: partial ctx + stats complete

        // ---- merge: global softmax rescale, full ctx locally ----
        if (tid < 256) {
            float gm = NEGV;
#pragma unroll
            for (int q = 0; q < 8; q++) gm = fmaxf(gm, sstat[q].x);
            float gs = 0.f, nc = 0.f;
#pragma unroll
            for (int q = 0; q < 8; q++) {
                float wq = expf(sstat[q].x - gm);
                gs += wq * sstat[q].y;
                nc += wq * pbuf[q][tid];
            }
            svec[nxt][tid] = nc / gs;
        }
        __syncthreads();

        // ---- stash own slice of [h | ctx] for epilogue GEMMs ----
        if (tid < 64) {
            int j = tid & 31;
            float* cr = g_cat + (size_t)(t * 16 + b) * 512;
            if (tid < 32) cr[r * 32 + j] = svec[nxt][256 + r * 32 + j];
            else          cr[256 + r * 32 + j] = svec[nxt][r * 32 + j];
        }
    }
}

// ---------------- zero the OOV logit region (float4) -----------------------
__global__ void zoov_k(float* __restrict__ out)
{
    int r = blockIdx.x;
    int v = threadIdx.x;
    if (v < 250)
        *reinterpret_cast<float4*>(out + (size_t)r * EXTV + Vc + v * 4) =
            make_float4(0.f, 0.f, 0.f, 0.f);
}

// ---------------- pointer-generator copy scatter ---------------------------
__global__ void scatter_k(float* __restrict__ out)
{
    __shared__ float se[Sc];
    __shared__ int sk[Sc];
    int bt = blockIdx.x;
    int b = bt / Tc, t = bt % Tc;
    int tid = threadIdx.x;
    if (tid < Sc) {
        se[tid] = g_energy[(size_t)(t * Bc + b) * Sc + tid];
        sk[tid] = g_skey[b * 512 + tid];
    }
    __syncthreads();
    if (tid < Sc) {
        int k = sk[tid], id = k >> 9;
        bool start = (tid == 0) || ((sk[tid - 1] >> 9) != id);
        if (start) {
            float m = se[k & 511];
            int j = tid + 1;
            while (j < Sc && (sk[j] >> 9) == id) {
                m = fmaxf(m, se[sk[j] & 511]);
                j++;
            }
            if (m > NEGV * 0.5f) out[(size_t)bt * EXTV + id] += m;
        }
    }
}

// ---------------- launch ----------------------------------------------------
extern "C" void kernel_launch(void* const* d_in, const int* in_sizes, int n_in,
                              void* d_out, int out_size)
{
    const int*   trg      = (const int*)d_in[0];
    const int*   ext_src  = (const int*)d_in[1];
    const int*   enc_mask = (const int*)d_in[2];
    const float* enc_out  = (const float*)d_in[3];
    const float* init_h   = (const float*)d_in[4];
    const float* init_c   = (const float*)d_in[5];
    const float* emb      = (const float*)d_in[6];
    const float* W_enc    = (const float*)d_in[7];
    const float* b_enc    = (const float*)d_in[8];
    const float* W_red    = (const float*)d_in[9];
    const float* b_red    = (const float*)d_in[10];
    const float* Wx       = (const float*)d_in[11];
    const float* Wh       = (const float*)d_in[12];
    const float* b_lstm   = (const float*)d_in[13];
    const float* W_cat    = (const float*)d_in[14];
    const float* b_cat    = (const float*)d_in[15];
    const float* W_out    = (const float*)d_in[16];
    const float* b_out    = (const float*)d_in[17];
    float* out = (float*)d_out;

    void* p;
    cudaGetSymbolAddress(&p, g_mem);  float* pMem  = (float*)p;
    cudaGetSymbolAddress(&p, g_A1);   float* pA1   = (float*)p;
    cudaGetSymbolAddress(&p, g_A2);   float* pA2   = (float*)p;
    cudaGetSymbolAddress(&p, g_bz);   float* pBz   = (float*)p;
    cudaGetSymbolAddress(&p, g_ze);   float* pZe   = (float*)p;
    cudaGetSymbolAddress(&p, g_cat);  float* pCat  = (float*)p;
    cudaGetSymbolAddress(&p, g_feat); float* pFeat = (float*)p;

    // 1) bz = b_red @ Wx + b_lstm
    bz_k<<<1, 1024>>>(b_red, Wx, b_lstm);
    // 2) B' pack+transpose (only needs W_out)
    packB_k<<<NPAD / 32, 256>>>(W_out);
    // 3) A1 = Wr_top @ Wx;  A2 = Wr_bot @ Wx
    gemm_k<0, 0, false><<<dim3(8, 2), 256>>>(W_red, Wx, nullptr, pA1,
                                             128, 1024, 128, 128, 1024, nullptr);
    gemm_k<0, 0, false><<<dim3(8, 4), 256>>>(W_red + 128 * 128, Wx, nullptr, pA2,
                                             256, 1024, 128, 128, 1024, nullptr);
    // 4) ze = emb[trg] @ A1 + bz
    gemm_k<0, 0, true><<<dim3(8, 25), 256>>>(emb, pA1, pBz, pZe,
                                             1600, 1024, 128, 128, 1024, trg);
    // 5) memories = encoder_outputs @ W_enc + b_enc
    gemm2_k<0, 0><<<dim3(1, 100), 256>>>(enc_out, W_enc, b_enc, pMem,
                                         6400, 256, 256, 256, 256);
    // 6) pack W2 slices
    pack_k<<<8 * 512, 128>>>(Wh);
    // 7) per-batch id sort
    sort_k<<<16, 512>>>(ext_src);
    // 8) clustered recurrence (512 threads, weights via L1)
    recur_k<<<128, 512>>>(init_h, init_c, enc_mask);
    // 9) feat = tanh(cat @ W_cat + b_cat)
    gemm2_k<1, 0><<<dim3(1, 25), 256>>>(pCat, W_cat, b_cat, pFeat,
                                        1600, 256, 512, 512, 256);
    // 10) A' pack
    packA_k<<<MPAD, 256>>>();
    // 11) zero the OOV region
    zoov_k<<<1600, 256>>>(out);
    // 12) logits via mma.sync bf16 (3-term split, K=768)
    mma_gemm_k<<<dim3(MPAD / 128, NPAD / 128), 256>>>(b_out, out);
    // 13) += scatter-max copy scores
    scatter_k<<<1600, 512>>>(out);
}